// round 2
// baseline (speedup 1.0000x reference)
#include <cuda_runtime.h>

#define TINYF 1e-6f
#define PIF   3.14159265358979323846f

// Per-lobe precomputed constants (L=128, H=16). SoA layout [k][l] for coalesced loads.
__device__ float g_a[16 * 128];   // A_l . M_k
__device__ float g_b[16 * 128];   // B_l . M_k
__device__ float g_c[16 * 128];   // C_l . M_k
__device__ float g_A[3 * 128];    // U*sinphi
__device__ float g_B[3 * 128];    // V*sinphi
__device__ float g_C[3 * 128];    // l*cosphi
__device__ float g_w[128];        // exp(sharp*(cosphi-1))

__global__ void precompute_kernel(const float* __restrict__ lobes,
                                  const float* __restrict__ lambdas,
                                  const float* __restrict__ rot,
                                  const float* __restrict__ W1) {
    __shared__ float sM[3][16];   // M = root_rot @ W1[3:6]  (3x16)
    int t = threadIdx.x;
    if (t < 48) {
        int d = t >> 4, k = t & 15;
        sM[d][k] = rot[d * 3 + 0] * W1[3 * 16 + k]
                 + rot[d * 3 + 1] * W1[4 * 16 + k]
                 + rot[d * 3 + 2] * W1[5 * 16 + k];
    }
    __syncthreads();

    int l = t;  // one thread per lobe, blockDim.x == 128
    float lx = lobes[l * 3 + 0], ly = lobes[l * 3 + 1], lz = lobes[l * 3 + 2];
    float inv = 1.f / (sqrtf(lx * lx + ly * ly + lz * lz) + TINYF);
    lx *= inv; ly *= inv; lz *= inv;

    // U = norm(cross(z, l)) = norm(-ly, lx, 0)
    float ux = -ly, uy = lx, uz = 0.f;
    float invu = 1.f / (sqrtf(ux * ux + uy * uy + uz * uz) + TINYF);
    ux *= invu; uy *= invu; uz *= invu;

    // V = norm(cross(l, U))
    float vx = ly * uz - lz * uy;
    float vy = lz * ux - lx * uz;
    float vz = lx * uy - ly * ux;
    float invv = 1.f / (sqrtf(vx * vx + vy * vy + vz * vz) + TINYF);
    vx *= invv; vy *= invv; vz *= invv;

    float sharp = lambdas[l];
    float rphi  = fminf(acosf(1.f - 1.f / sharp), PIF / 3.f);
    float sp = sinf(rphi), cp = cosf(rphi);

    float Ax = ux * sp, Ay = uy * sp, Az = uz * sp;
    float Bx = vx * sp, By = vy * sp, Bz = vz * sp;
    float Cx = lx * cp, Cy = ly * cp, Cz = lz * cp;

    g_A[l] = Ax; g_A[128 + l] = Ay; g_A[256 + l] = Az;
    g_B[l] = Bx; g_B[128 + l] = By; g_B[256 + l] = Bz;
    g_C[l] = Cx; g_C[128 + l] = Cy; g_C[256 + l] = Cz;
    g_w[l] = expf(sharp * (cp - 1.f));

#pragma unroll
    for (int k = 0; k < 16; k++) {
        g_a[k * 128 + l] = Ax * sM[0][k] + Ay * sM[1][k] + Az * sM[2][k];
        g_b[k * 128 + l] = Bx * sM[0][k] + By * sM[1][k] + Bz * sM[2][k];
        g_c[k * 128 + l] = Cx * sM[0][k] + Cy * sM[1][k] + Cz * sM[2][k];
    }
}

// One block per point n (128 threads = 128 lobes), each thread loops S=8 samples.
__global__ __launch_bounds__(128) void vis_kernel(
    const float* __restrict__ points,
    const float* __restrict__ normals,
    const float* __restrict__ r,       // (N, 128, 8)
    const float* __restrict__ W1,      // (6, 16)
    const float* __restrict__ b1,      // (16,)
    const float* __restrict__ W2,      // (16, 1)
    const float* __restrict__ b2,      // (1,)
    float* __restrict__ out)           // (N, 128)
{
    const int n = blockIdx.x;
    const int l = threadIdx.x;

    __shared__ float s_base[16];  // points[n] @ W1[:3] + b1
    __shared__ float s_nrm[3];
    __shared__ float s_w2[16];
    __shared__ float s_b2;

    if (l < 16) {
        float px = points[n * 3 + 0], py = points[n * 3 + 1], pz = points[n * 3 + 2];
        s_base[l] = fmaf(px, W1[0 * 16 + l],
                    fmaf(py, W1[1 * 16 + l],
                    fmaf(pz, W1[2 * 16 + l], b1[l])));
        s_w2[l] = W2[l];
    }
    if (l < 3)  s_nrm[l] = normals[n * 3 + l];
    if (l == 16) s_b2 = b2[0];
    __syncthreads();

    const float nx = s_nrm[0], ny = s_nrm[1], nz = s_nrm[2];
    const float an = fmaf(g_A[l], nx, fmaf(g_A[128 + l], ny, g_A[256 + l] * nz));
    const float bn = fmaf(g_B[l], nx, fmaf(g_B[128 + l], ny, g_B[256 + l] * nz));
    const float cn = fmaf(g_C[l], nx, fmaf(g_C[128 + l], ny, g_C[256 + l] * nz));
    const float wl = g_w[l];

    float a[16], b[16], base2[16], w2r[16];
#pragma unroll
    for (int k = 0; k < 16; k++) {
        a[k]     = g_a[k * 128 + l];
        b[k]     = g_b[k * 128 + l];
        base2[k] = s_base[k] - g_c[k * 128 + l];
        w2r[k]   = s_w2[k];
    }
    const float bb2 = s_b2;

    // 8 random thetas for this (n,l): two coalesced float4 loads
    const float* rbase = r + (size_t)(n * 128 + l) * 8;
    const float4 r0 = *reinterpret_cast<const float4*>(rbase);
    const float4 r1 = *reinterpret_cast<const float4*>(rbase + 4);
    float rr[8] = {r0.x, r0.y, r0.z, r0.w, r1.x, r1.y, r1.z, r1.w};

    float vsum = 0.f;
#pragma unroll
    for (int s = 0; s < 8; s++) {
        // r_theta = (r/S + s/S)*2pi = (r + s)*(pi/4)
        float theta = (rr[s] + (float)s) * (PIF * 0.25f);
        float st, ct;
        __sincosf(theta, &st, &ct);

        float cosn = fmaf(ct, an, fmaf(st, bn, cn));

        float logit = bb2;
#pragma unroll
        for (int k = 0; k < 16; k++) {
            float h = fmaf(ct, -a[k], fmaf(st, -b[k], base2[k]));
            h = fmaxf(h, 0.f);
            logit = fmaf(h, w2r[k], logit);
        }
        float vis = __fdividef(1.f, 1.f + __expf(-logit));
        vsum += (cosn > TINYF) ? vis : 0.f;
    }

    // sum(vis*w)/(sum(w)+TINY) with w constant over s
    out[n * 128 + l] = __fdividef(wl * vsum, 8.f * wl + TINYF);
}

extern "C" void kernel_launch(void* const* d_in, const int* in_sizes, int n_in,
                              void* d_out, int out_size) {
    const float* points  = (const float*)d_in[0];
    const float* normals = (const float*)d_in[1];
    const float* rot     = (const float*)d_in[2];
    const float* lobes   = (const float*)d_in[3];
    const float* lambdas = (const float*)d_in[4];
    const float* r       = (const float*)d_in[5];
    const float* W1      = (const float*)d_in[6];
    const float* b1      = (const float*)d_in[7];
    const float* W2      = (const float*)d_in[8];
    const float* b2      = (const float*)d_in[9];

    const int N = in_sizes[0] / 3;   // 8192

    precompute_kernel<<<1, 128>>>(lobes, lambdas, rot, W1);
    vis_kernel<<<N, 128>>>(points, normals, r, W1, b1, W2, b2, (float*)d_out);
}

// round 3
// speedup vs baseline: 1.1445x; 1.1445x over previous
#include <cuda_runtime.h>

typedef unsigned long long ull;

#define TINYF 1e-6f
#define PIF   3.14159265358979323846f

// Packed per-lobe constants: pair (2k,2k+1) per element, SoA [kpair][l].
__device__ float2 g_na2[8 * 128];   // (-a_{2k}, -a_{2k+1})
__device__ float2 g_nb2[8 * 128];   // (-b_{2k}, -b_{2k+1})
__device__ float2 g_nc2[8 * 128];   // (-c_{2k}, -c_{2k+1})
__device__ float  g_A[3 * 128];     // U*sinphi
__device__ float  g_B[3 * 128];     // V*sinphi
__device__ float  g_C[3 * 128];     // l*cosphi
__device__ float  g_w[128];         // exp(sharp*(cosphi-1))
__device__ float  g_linA[128];      // sum_k w2h_k * (-a_kl)
__device__ float  g_linB[128];      // sum_k w2h_k * (-b_kl)
__device__ float  g_linC[128];      // sum_k w2h_k * (-c_kl)

__device__ __forceinline__ ull pack2(float x, float y) {
    ull r; asm("mov.b64 %0, {%1, %2};" : "=l"(r) : "f"(x), "f"(y)); return r;
}
__device__ __forceinline__ void unpack2(ull v, float& x, float& y) {
    asm("mov.b64 {%0, %1}, %2;" : "=f"(x), "=f"(y) : "l"(v));
}
__device__ __forceinline__ ull fma2(ull a, ull b, ull c) {
    ull d; asm("fma.rn.f32x2 %0, %1, %2, %3;" : "=l"(d) : "l"(a), "l"(b), "l"(c)); return d;
}
__device__ __forceinline__ ull add2(ull a, ull b) {
    ull d; asm("add.rn.f32x2 %0, %1, %2;" : "=l"(d) : "l"(a), "l"(b)); return d;
}

__global__ void precompute_kernel(const float* __restrict__ lobes,
                                  const float* __restrict__ lambdas,
                                  const float* __restrict__ rot,
                                  const float* __restrict__ W1,
                                  const float* __restrict__ W2) {
    __shared__ float sM[3][16];   // M = root_rot @ W1[3:6]  (3x16)
    __shared__ float sw2h[16];    // W2[k] / 2
    int t = threadIdx.x;
    if (t < 48) {
        int d = t >> 4, k = t & 15;
        sM[d][k] = rot[d * 3 + 0] * W1[3 * 16 + k]
                 + rot[d * 3 + 1] * W1[4 * 16 + k]
                 + rot[d * 3 + 2] * W1[5 * 16 + k];
    }
    if (t < 16) sw2h[t] = 0.5f * W2[t];
    __syncthreads();

    int l = t;  // blockDim.x == 128
    float lx = lobes[l * 3 + 0], ly = lobes[l * 3 + 1], lz = lobes[l * 3 + 2];
    float inv = 1.f / (sqrtf(lx * lx + ly * ly + lz * lz) + TINYF);
    lx *= inv; ly *= inv; lz *= inv;

    float ux = -ly, uy = lx, uz = 0.f;
    float invu = 1.f / (sqrtf(ux * ux + uy * uy) + TINYF);
    ux *= invu; uy *= invu;

    float vx = ly * uz - lz * uy;
    float vy = lz * ux - lx * uz;
    float vz = lx * uy - ly * ux;
    float invv = 1.f / (sqrtf(vx * vx + vy * vy + vz * vz) + TINYF);
    vx *= invv; vy *= invv; vz *= invv;

    float sharp = lambdas[l];
    float rphi  = fminf(acosf(1.f - 1.f / sharp), PIF / 3.f);
    float sp = sinf(rphi), cp = cosf(rphi);

    float Ax = ux * sp, Ay = uy * sp, Az = uz * sp;
    float Bx = vx * sp, By = vy * sp, Bz = vz * sp;
    float Cx = lx * cp, Cy = ly * cp, Cz = lz * cp;

    g_A[l] = Ax; g_A[128 + l] = Ay; g_A[256 + l] = Az;
    g_B[l] = Bx; g_B[128 + l] = By; g_B[256 + l] = Bz;
    g_C[l] = Cx; g_C[128 + l] = Cy; g_C[256 + l] = Cz;
    g_w[l] = expf(sharp * (cp - 1.f));

    float na[16], nb[16], nc[16];
#pragma unroll
    for (int k = 0; k < 16; k++) {
        float a = Ax * sM[0][k] + Ay * sM[1][k] + Az * sM[2][k];
        float b = Bx * sM[0][k] + By * sM[1][k] + Bz * sM[2][k];
        float c = Cx * sM[0][k] + Cy * sM[1][k] + Cz * sM[2][k];
        na[k] = -a; nb[k] = -b; nc[k] = -c;
    }

    float A_ = 0.f, B_ = 0.f, C_ = 0.f;
#pragma unroll
    for (int k = 0; k < 16; k++) {
        A_ = fmaf(sw2h[k], na[k], A_);
        B_ = fmaf(sw2h[k], nb[k], B_);
        C_ = fmaf(sw2h[k], nc[k], C_);
    }
    g_linA[l] = A_; g_linB[l] = B_; g_linC[l] = C_;

#pragma unroll
    for (int kp = 0; kp < 8; kp++) {
        g_na2[kp * 128 + l] = make_float2(na[2 * kp], na[2 * kp + 1]);
        g_nb2[kp * 128 + l] = make_float2(nb[2 * kp], nb[2 * kp + 1]);
        g_nc2[kp * 128 + l] = make_float2(nc[2 * kp], nc[2 * kp + 1]);
    }
}

// One block per point n (128 threads = 128 lobes); S=8 samples in 2 chunks of 4.
__global__ __launch_bounds__(128) void vis_kernel(
    const float* __restrict__ points,
    const float* __restrict__ normals,
    const float* __restrict__ r,       // (N, 128, 8)
    const float* __restrict__ W1,      // (6, 16)
    const float* __restrict__ b1,      // (16,)
    const float* __restrict__ W2,      // (16, 1)
    const float* __restrict__ b2,      // (1,)
    float* __restrict__ out)           // (N, 128)
{
    const int n = blockIdx.x;
    const int l = threadIdx.x;

    __shared__ float s_base[16];   // points[n] @ W1[:3] + b1
    __shared__ ull   s_basep[8];   // packed pairs of s_base
    __shared__ float s_w2h[16];    // W2/2
    __shared__ float s_nrm[3];
    __shared__ float s_lin0;       // b2 + sum_k w2h_k * s_base[k]

    if (l < 16) {
        float px = points[n * 3 + 0], py = points[n * 3 + 1], pz = points[n * 3 + 2];
        s_base[l] = fmaf(px, W1[0 * 16 + l],
                    fmaf(py, W1[1 * 16 + l],
                    fmaf(pz, W1[2 * 16 + l], b1[l])));
        s_w2h[l] = 0.5f * W2[l];
    }
    if (l < 3) s_nrm[l] = normals[n * 3 + l];
    __syncthreads();

    if (l == 0) {
        float c1 = b2[0];
#pragma unroll
        for (int k = 0; k < 16; k++) c1 = fmaf(s_w2h[k], s_base[k], c1);
        s_lin0 = c1;
    }
    if (l < 8) s_basep[l] = pack2(s_base[2 * l], s_base[2 * l + 1]);
    __syncthreads();

    // Per-(n,l) scalars
    const float nx = s_nrm[0], ny = s_nrm[1], nz = s_nrm[2];
    const float an = fmaf(g_A[l], nx, fmaf(g_A[128 + l], ny, g_A[256 + l] * nz));
    const float bn = fmaf(g_B[l], nx, fmaf(g_B[128 + l], ny, g_B[256 + l] * nz));
    const float cn = fmaf(g_C[l], nx, fmaf(g_C[128 + l], ny, g_C[256 + l] * nz));
    const float wl = g_w[l];
    const float Ap = g_linA[l], Bp = g_linB[l];
    const float lin0 = s_lin0 + g_linC[l];

    // Packed per-lobe MLP constants (held in registers across all samples)
    ull na2[8], nb2[8], b22[8];
    float w2h[16];
    const ull* gna = reinterpret_cast<const ull*>(g_na2);
    const ull* gnb = reinterpret_cast<const ull*>(g_nb2);
    const ull* gnc = reinterpret_cast<const ull*>(g_nc2);
#pragma unroll
    for (int kp = 0; kp < 8; kp++) {
        na2[kp] = gna[kp * 128 + l];
        nb2[kp] = gnb[kp * 128 + l];
        b22[kp] = add2(s_basep[kp], gnc[kp * 128 + l]);
    }
#pragma unroll
    for (int k = 0; k < 16; k++) w2h[k] = s_w2h[k];

    const float* rbase = r + (size_t)(n * 128 + l) * 8;

    float vsum = 0.f;
#pragma unroll
    for (int chunk = 0; chunk < 2; chunk++) {
        const float4 rv = *reinterpret_cast<const float4*>(rbase + chunk * 4);
        float rr[4] = {rv.x, rv.y, rv.z, rv.w};
#pragma unroll
        for (int j = 0; j < 4; j++) {
            const int s = chunk * 4 + j;
            float theta = (rr[j] + (float)s) * (PIF * 0.25f);
            float st, ct;
            __sincosf(theta, &st, &ct);

            float cosn = fmaf(ct, an, fmaf(st, bn, cn));

            ull ct2 = pack2(ct, ct);
            ull st2 = pack2(st, st);

            float acc0 = 0.f, acc1 = 0.f;
#pragma unroll
            for (int kp = 0; kp < 8; kp++) {
                ull h2 = fma2(ct2, na2[kp], fma2(st2, nb2[kp], b22[kp]));
                float hlo, hhi;
                unpack2(h2, hlo, hhi);
                acc0 = fmaf(fabsf(hlo), w2h[2 * kp + 0], acc0);
                acc1 = fmaf(fabsf(hhi), w2h[2 * kp + 1], acc1);
            }
            // logit = b2 + sum w2h*h (linear part) + sum w2h*|h|
            float logit = fmaf(ct, Ap, fmaf(st, Bp, lin0)) + acc0 + acc1;

            float vis = __fdividef(1.f, 1.f + __expf(-logit));
            vsum += (cosn > TINYF) ? vis : 0.f;
        }
    }

    out[n * 128 + l] = __fdividef(wl * vsum, 8.f * wl + TINYF);
}

extern "C" void kernel_launch(void* const* d_in, const int* in_sizes, int n_in,
                              void* d_out, int out_size) {
    const float* points  = (const float*)d_in[0];
    const float* normals = (const float*)d_in[1];
    const float* rot     = (const float*)d_in[2];
    const float* lobes   = (const float*)d_in[3];
    const float* lambdas = (const float*)d_in[4];
    const float* r       = (const float*)d_in[5];
    const float* W1      = (const float*)d_in[6];
    const float* b1      = (const float*)d_in[7];
    const float* W2      = (const float*)d_in[8];
    const float* b2      = (const float*)d_in[9];

    const int N = in_sizes[0] / 3;   // 8192

    precompute_kernel<<<1, 128>>>(lobes, lambdas, rot, W1, W2);
    vis_kernel<<<N, 128>>>(points, normals, r, W1, b1, W2, b2, (float*)d_out);
}